// round 12
// baseline (speedup 1.0000x reference)
#include <cuda_runtime.h>
#include <cstdint>

// Masked mean over first xs_len[b] rows of xs[b]: out[b][d] = sum_{s<L} xs[b][s][d] / L
// xs: [16, 4096, 512] f32, xs_len: [16] (int32 OR int64 -- decoded at runtime), out: [16, 512] f32
// Single fused kernel: R8's 256-thread split loader + "last block per batch"
// in-kernel reduction (overlaps other batches' loads; only the globally last
// batch's reduction is exposed tail).

#define B 16
#define S 4096
#define D 512
#define D4 (D / 4)                   // 128 float4 per row
#define SPLIT 64
#define ROWS_PER_SPLIT (S / SPLIT)   // 64

// Scratch partials: [B][SPLIT][D4] float4 = 2 MiB. Only splits with s0 < L are
// written; the reducing block reads exactly those (n_valid) -> deterministic.
__device__ float4 g_partial[B * SPLIT * D4];
// Per-batch arrival counters. Statically zero-initialized; the last block of
// each batch resets its counter before exiting -> graph-replay safe.
__device__ int g_count[B];

// Robust length decode: int64 value lies in [1, S]; an int32 buffer read as
// int64 packs two lengths (both >= 1) and falls outside [1, S].
__device__ __forceinline__ int decode_len(const void* xs_len, int b) {
    long long v64 = ((const long long*)xs_len)[b];
    if (v64 >= 1 && v64 <= (long long)S) return (int)v64;
    return ((const int*)xs_len)[b];
}

// grid (SPLIT, B), 256 threads arranged as (half, col):
//   col  = t & 127  -> float4 column
//   half = t >> 7   -> rows s0+half, s0+half+2, ... (stride 2)
__global__ void __launch_bounds__(256, 6)
mean_fused_kernel(const float* __restrict__ xs,
                  const void* __restrict__ xs_len,
                  float* __restrict__ out) {
    const int sp   = blockIdx.x;
    const int b    = blockIdx.y;
    const int t    = threadIdx.x;
    const int col  = t & (D4 - 1);
    const int half = t >> 7;

    const int L = decode_len(xs_len, b);
    const int n_valid = (L + ROWS_PER_SPLIT - 1) / ROWS_PER_SPLIT;  // [1,64]

    __shared__ float4 sm[256];

    const int s0 = sp * ROWS_PER_SPLIT;
    if (s0 < L) {
        int s1 = s0 + ROWS_PER_SPLIT;
        if (s1 > L) s1 = L;

        const float4* __restrict__ base =
            reinterpret_cast<const float4*>(xs + (size_t)b * S * D) + col;

        float4 acc = make_float4(0.f, 0.f, 0.f, 0.f);

        int s = s0 + half;
        // 8 independent LDG.128 in flight (rows s, s+2, ..., s+14)
        for (; s + 14 < s1; s += 16) {
            float4 v0 = base[(size_t)(s +  0) * D4];
            float4 v1 = base[(size_t)(s +  2) * D4];
            float4 v2 = base[(size_t)(s +  4) * D4];
            float4 v3 = base[(size_t)(s +  6) * D4];
            float4 v4 = base[(size_t)(s +  8) * D4];
            float4 v5 = base[(size_t)(s + 10) * D4];
            float4 v6 = base[(size_t)(s + 12) * D4];
            float4 v7 = base[(size_t)(s + 14) * D4];
            acc.x += (v0.x + v1.x) + (v2.x + v3.x) + (v4.x + v5.x) + (v6.x + v7.x);
            acc.y += (v0.y + v1.y) + (v2.y + v3.y) + (v4.y + v5.y) + (v6.y + v7.y);
            acc.z += (v0.z + v1.z) + (v2.z + v3.z) + (v4.z + v5.z) + (v6.z + v7.z);
            acc.w += (v0.w + v1.w) + (v2.w + v3.w) + (v4.w + v5.w) + (v6.w + v7.w);
        }
        for (; s < s1; s += 2) {
            float4 v = base[(size_t)s * D4];
            acc.x += v.x; acc.y += v.y; acc.z += v.z; acc.w += v.w;
        }

        sm[t] = acc;
        __syncthreads();

        if (half == 0) {
            float4 o = sm[t + 128];
            acc.x += o.x; acc.y += o.y; acc.z += o.z; acc.w += o.w;
            g_partial[(b * SPLIT + sp) * D4 + col] = acc;
        }
        // acc dies here: nothing fp-live across the arrival -> low reg pressure
    }

    // Arrival protocol (threadFenceReduction pattern): make this block's
    // partial globally visible, then count arrivals for batch b.
    __threadfence();
    __shared__ int is_last;
    __syncthreads();
    if (t == 0) {
        int prev = atomicAdd(&g_count[b], 1);
        is_last = (prev == SPLIT - 1);
    }
    __syncthreads();

    if (!is_last) return;

    // Last arrival for batch b: all valid partials are globally visible.
    __threadfence();   // acquire side: order the atomic read before the loads

    // 256 threads: (half, col). Each half sums splits half, half+2, ... < n_valid
    // with independent loads (L2-hot), then a 2-way smem fold. Fixed order.
    const float4* __restrict__ pbase = &g_partial[(size_t)b * SPLIT * D4 + col];

    float4 r = make_float4(0.f, 0.f, 0.f, 0.f);
    int k = half;
    for (; k + 6 < n_valid; k += 8) {
        float4 v0 = pbase[(size_t)(k + 0) * D4];
        float4 v1 = pbase[(size_t)(k + 2) * D4];
        float4 v2 = pbase[(size_t)(k + 4) * D4];
        float4 v3 = pbase[(size_t)(k + 6) * D4];
        r.x += (v0.x + v1.x) + (v2.x + v3.x);
        r.y += (v0.y + v1.y) + (v2.y + v3.y);
        r.z += (v0.z + v1.z) + (v2.z + v3.z);
        r.w += (v0.w + v1.w) + (v2.w + v3.w);
    }
    for (; k < n_valid; k += 2) {
        float4 v = pbase[(size_t)k * D4];
        r.x += v.x; r.y += v.y; r.z += v.z; r.w += v.w;
    }

    sm[t] = r;
    __syncthreads();

    if (half == 0) {
        float4 o = sm[t + 128];
        r.x += o.x; r.y += o.y; r.z += o.z; r.w += o.w;
        const float inv = 1.0f / (float)L;
        r.x *= inv; r.y *= inv; r.z *= inv; r.w *= inv;
        reinterpret_cast<float4*>(out)[b * D4 + col] = r;
        if (t == 0) g_count[b] = 0;   // reset for next graph replay
    }
}

extern "C" void kernel_launch(void* const* d_in, const int* in_sizes, int n_in,
                              void* d_out, int out_size) {
    const float* xs = (const float*)d_in[0];
    const void* xs_len = d_in[1];
    float* out = (float*)d_out;

    dim3 grid(SPLIT, B);
    mean_fused_kernel<<<grid, 256>>>(xs, xs_len, out);
}

// round 13
// speedup vs baseline: 1.1579x; 1.1579x over previous
#include <cuda_runtime.h>
#include <cstdint>

// Masked mean over first xs_len[b] rows of xs[b]: out[b][d] = sum_{s<L} xs[b][s][d] / L
// xs: [16, 4096, 512] f32, xs_len: [16] (int32 OR int64 -- decoded at runtime), out: [16, 512] f32
// Single fused kernel: R8's 256-thread split loader + "last block per batch"
// reduction. Arrival uses one acq_rel atomic (no MEMBAR); reduction lives in a
// __noinline__ function so the loader's register file / MLP stays intact.

#define B 16
#define S 4096
#define D 512
#define D4 (D / 4)                   // 128 float4 per row
#define SPLIT 64
#define ROWS_PER_SPLIT (S / SPLIT)   // 64

// Scratch partials: [B][SPLIT][D4] float4 = 2 MiB. Only splits with s0 < L are
// written; the reducing block reads exactly those (n_valid) -> deterministic.
__device__ float4 g_partial[B * SPLIT * D4];
// Per-batch arrival counters. Statically zero-initialized; the last block of
// each batch resets its counter before exiting -> graph-replay safe.
__device__ int g_count[B];

// Robust length decode: int64 value lies in [1, S]; an int32 buffer read as
// int64 packs two lengths (both >= 1) and falls outside [1, S].
__device__ __forceinline__ int decode_len(const void* xs_len, int b) {
    long long v64 = ((const long long*)xs_len)[b];
    if (v64 >= 1 && v64 <= (long long)S) return (int)v64;
    return ((const int*)xs_len)[b];
}

// acq_rel GPU-scope atomic add: release (prior stores, incl. other threads'
// stores ordered via bar.sync, become visible) + acquire (subsequent loads see
// all partials released by earlier arrivals). No full MEMBAR needed anywhere.
__device__ __forceinline__ int atomic_add_acq_rel(int* p, int v) {
    int old;
    asm volatile("atom.acq_rel.gpu.add.s32 %0, [%1], %2;"
                 : "=r"(old) : "l"(p), "r"(v) : "memory");
    return old;
}

// Reduction tail for one batch. __noinline__ so its registers don't inflate
// the loader's allocation (it runs in exactly one block per batch).
__device__ __noinline__ void reduce_batch(float4* sm, float* out,
                                          int b, int L, int n_valid,
                                          int t, int col, int half) {
    const float4* __restrict__ pbase = &g_partial[(size_t)b * SPLIT * D4 + col];

    float4 r = make_float4(0.f, 0.f, 0.f, 0.f);
    int k = half;
    for (; k + 6 < n_valid; k += 8) {
        float4 v0 = pbase[(size_t)(k + 0) * D4];
        float4 v1 = pbase[(size_t)(k + 2) * D4];
        float4 v2 = pbase[(size_t)(k + 4) * D4];
        float4 v3 = pbase[(size_t)(k + 6) * D4];
        r.x += (v0.x + v1.x) + (v2.x + v3.x);
        r.y += (v0.y + v1.y) + (v2.y + v3.y);
        r.z += (v0.z + v1.z) + (v2.z + v3.z);
        r.w += (v0.w + v1.w) + (v2.w + v3.w);
    }
    for (; k < n_valid; k += 2) {
        float4 v = pbase[(size_t)k * D4];
        r.x += v.x; r.y += v.y; r.z += v.z; r.w += v.w;
    }

    sm[t] = r;
    __syncthreads();

    if (half == 0) {
        float4 o = sm[t + 128];
        r.x += o.x; r.y += o.y; r.z += o.z; r.w += o.w;
        const float inv = 1.0f / (float)L;
        r.x *= inv; r.y *= inv; r.z *= inv; r.w *= inv;
        reinterpret_cast<float4*>(out)[b * D4 + col] = r;
        if (t == 0) g_count[b] = 0;   // reset for next graph replay
    }
}

// grid (SPLIT, B), 256 threads arranged as (half, col):
//   col  = t & 127  -> float4 column
//   half = t >> 7   -> rows s0+half, s0+half+2, ... (stride 2)
__global__ void __launch_bounds__(256)
mean_fused_kernel(const float* __restrict__ xs,
                  const void* __restrict__ xs_len,
                  float* __restrict__ out) {
    const int sp   = blockIdx.x;
    const int b    = blockIdx.y;
    const int t    = threadIdx.x;
    const int col  = t & (D4 - 1);
    const int half = t >> 7;

    const int L = decode_len(xs_len, b);
    const int n_valid = (L + ROWS_PER_SPLIT - 1) / ROWS_PER_SPLIT;  // [1,64]

    __shared__ float4 sm[256];

    const int s0 = sp * ROWS_PER_SPLIT;
    if (s0 < L) {
        int s1 = s0 + ROWS_PER_SPLIT;
        if (s1 > L) s1 = L;

        const float4* __restrict__ base =
            reinterpret_cast<const float4*>(xs + (size_t)b * S * D) + col;

        float4 acc = make_float4(0.f, 0.f, 0.f, 0.f);

        int s = s0 + half;
        // 8 independent LDG.128 in flight (rows s, s+2, ..., s+14)
        for (; s + 14 < s1; s += 16) {
            float4 v0 = base[(size_t)(s +  0) * D4];
            float4 v1 = base[(size_t)(s +  2) * D4];
            float4 v2 = base[(size_t)(s +  4) * D4];
            float4 v3 = base[(size_t)(s +  6) * D4];
            float4 v4 = base[(size_t)(s +  8) * D4];
            float4 v5 = base[(size_t)(s + 10) * D4];
            float4 v6 = base[(size_t)(s + 12) * D4];
            float4 v7 = base[(size_t)(s + 14) * D4];
            acc.x += (v0.x + v1.x) + (v2.x + v3.x) + (v4.x + v5.x) + (v6.x + v7.x);
            acc.y += (v0.y + v1.y) + (v2.y + v3.y) + (v4.y + v5.y) + (v6.y + v7.y);
            acc.z += (v0.z + v1.z) + (v2.z + v3.z) + (v4.z + v5.z) + (v6.z + v7.z);
            acc.w += (v0.w + v1.w) + (v2.w + v3.w) + (v4.w + v5.w) + (v6.w + v7.w);
        }
        for (; s < s1; s += 2) {
            float4 v = base[(size_t)s * D4];
            acc.x += v.x; acc.y += v.y; acc.z += v.z; acc.w += v.w;
        }

        sm[t] = acc;
        __syncthreads();

        if (half == 0) {
            float4 o = sm[t + 128];
            acc.x += o.x; acc.y += o.y; acc.z += o.z; acc.w += o.w;
            g_partial[(b * SPLIT + sp) * D4 + col] = acc;
        }
        __syncthreads();   // partial STG issued by all halves before arrival
    }

    // Arrival: one acq_rel atomic by t0. bar.sync above orders the whole
    // block's stores before it (cumulative release).
    __shared__ int is_last;
    if (t == 0) {
        int prev = atomic_add_acq_rel(&g_count[b], 1);
        is_last = (prev == SPLIT - 1);
    }
    __syncthreads();

    if (is_last)
        reduce_batch(sm, out, b, L, n_valid, t, col, half);
}

extern "C" void kernel_launch(void* const* d_in, const int* in_sizes, int n_in,
                              void* d_out, int out_size) {
    const float* xs = (const float*)d_in[0];
    const void* xs_len = d_in[1];
    float* out = (float*)d_out;

    dim3 grid(SPLIT, B);
    mean_fused_kernel<<<grid, 256>>>(xs, xs_len, out);
}